// round 17
// baseline (speedup 1.0000x reference)
#include <cuda_runtime.h>
#include <cuda_bf16.h>
#include <cstdint>

#define TSTEPS 256

__device__ float zx_buf[134217728];   // [2048*256 rows][256 cols] fp32 scratch (512 MB)

// ---------- helpers ----------
__device__ __forceinline__ unsigned long long pack2(float x, float y) {
  unsigned long long r; asm("mov.b64 %0, {%1, %2};" : "=l"(r) : "f"(x), "f"(y)); return r;
}
__device__ __forceinline__ float2 unpack2(unsigned long long v) {
  float2 f; asm("mov.b64 {%0, %1}, %2;" : "=f"(f.x), "=f"(f.y) : "l"(v)); return f;
}
#define FMA2(d, a, b) asm("fma.rn.f32x2 %0, %1, %2, %0;" : "+l"(d) : "l"(a), "l"(b))
#define ADD2(d, s)    asm("add.rn.f32x2 %0, %0, %1;" : "+l"(d) : "l"(s))
__device__ __forceinline__ float sigm(float x) { return __fdividef(1.f, 1.f + __expf(-x)); }
__device__ __forceinline__ float tanhx(float x) {
  float xx = fminf(fmaxf(x, -15.f), 15.f);
  float e = __expf(2.f * xx);
  return __fdividef(e - 1.f, e + 1.f);
}
__device__ __forceinline__ uint32_t smem_u32(const void* p) {
  return (uint32_t)__cvta_generic_to_shared(p);
}
__device__ __forceinline__ uint32_t split_pack(float a, float b, uint32_t& lo) {
  __nv_bfloat16 ha = __float2bfloat16(a), hb = __float2bfloat16(b);
  __nv_bfloat16 la = __float2bfloat16(a - __bfloat162float(ha));
  __nv_bfloat16 lb = __float2bfloat16(b - __bfloat162float(hb));
  lo = (uint32_t)__bfloat16_as_ushort(la) | ((uint32_t)__bfloat16_as_ushort(lb) << 16);
  return (uint32_t)__bfloat16_as_ushort(ha) | ((uint32_t)__bfloat16_as_ushort(hb) << 16);
}
#define LDM4(r0, r1, r2, r3, addr) \
  asm volatile("ldmatrix.sync.aligned.m8n8.x4.shared.b16 {%0,%1,%2,%3}, [%4];" \
               : "=r"(r0), "=r"(r1), "=r"(r2), "=r"(r3) : "r"(addr))
#define MMA16816(c, a, b0, b1) \
  asm volatile("mma.sync.aligned.m16n8k16.row.col.f32.bf16.bf16.f32 " \
               "{%0,%1,%2,%3}, {%4,%5,%6,%7}, {%8,%9}, {%0,%1,%2,%3};" \
               : "+f"((c)[0]), "+f"((c)[1]), "+f"((c)[2]), "+f"((c)[3]) \
               : "r"((a)[0]), "r"((a)[1]), "r"((a)[2]), "r"((a)[3]), "r"(b0), "r"(b1))

// ============ Kernel 1: zx = X @ Wx via mma.sync bf16 3-pass split (unchanged) ============
#define APITCH 136
#define BPITCH 136
#define K1_AHI   0
#define K1_ALO   34816
#define K1_BHI   69632
#define K1_BLO   139264
#define K1_TOTAL 208896

__global__ void __launch_bounds__(256, 1)
zx_gemm_kernel(const float* __restrict__ obss, const float* __restrict__ acts,
               const float* __restrict__ Wg) {
  extern __shared__ char sm[];
  const int tid = threadIdx.x, lane = tid & 31, warp = tid >> 5;
  const int warp_m = warp & 3, warp_n = warp >> 2;
  const uint32_t sb = smem_u32(sm);

  {   // convert B = Wx^T once: thread = n (0..255), all 128 k
    const int n = tid;
#pragma unroll 4
    for (int k = 0; k < 128; k += 2) {
      float w0 = Wg[(size_t)k * 256 + n];
      float w1 = Wg[(size_t)(k + 1) * 256 + n];
      uint32_t lo, hi = split_pack(w0, w1, lo);
      uint32_t bo = (uint32_t)(n * BPITCH + k) * 2;
      *(uint32_t*)(sm + K1_BHI + bo) = hi;
      *(uint32_t*)(sm + K1_BLO + bo) = lo;
    }
  }

  const uint32_t laneA = ((uint32_t)(lane & 15) * APITCH + (uint32_t)(lane >> 4) * 8) * 2;
  const uint32_t laneB = (((uint32_t)(lane & 7) + (uint32_t)((lane >> 4) << 3)) * BPITCH +
                          (uint32_t)((lane >> 3) & 1) * 8) * 2;
  const int arow = tid >> 1, ahalf = tid & 1;
  const int er = lane >> 2, ec = (lane & 3) * 2;

  for (int tile = blockIdx.x; tile < 4096; tile += gridDim.x) {
    const int m0 = tile * 128;
    {   // stage + split-convert A rows
      const int m = m0 + arow, nn = m >> 8, tt = m & 255;
      const float* so = obss + ((size_t)nn * 256 + tt) * 96;
      const float* sa = acts + ((size_t)nn * 256 + tt) * 32;
#pragma unroll
      for (int i = 0; i < 16; i++) {
        int c = ahalf * 64 + 4 * i;
        float4 v = (c < 96) ? *(const float4*)(so + c) : *(const float4*)(sa + (c - 96));
        uint32_t lo0, hi0 = split_pack(v.x, v.y, lo0);
        uint32_t lo1, hi1 = split_pack(v.z, v.w, lo1);
        uint32_t bo = (uint32_t)(arow * APITCH + c) * 2;
        *(uint32_t*)(sm + K1_AHI + bo)     = hi0;
        *(uint32_t*)(sm + K1_AHI + bo + 4) = hi1;
        *(uint32_t*)(sm + K1_ALO + bo)     = lo0;
        *(uint32_t*)(sm + K1_ALO + bo + 4) = lo1;
      }
    }
    __syncthreads();

    float acc[2][16][4];
#pragma unroll
    for (int mt = 0; mt < 2; mt++)
#pragma unroll
      for (int nt = 0; nt < 16; nt++)
#pragma unroll
        for (int j = 0; j < 4; j++) acc[mt][nt][j] = 0.f;

    for (int p = 0; p < 3; p++) {   // AhiBhi, AhiBlo, AloBhi
      uint32_t abase = sb + ((p < 2) ? K1_AHI : K1_ALO) +
                       (uint32_t)(warp_m * 32) * APITCH * 2 + laneA;
      uint32_t bbase = sb + ((p == 1) ? K1_BLO : K1_BHI) +
                       (uint32_t)(warp_n * 128) * BPITCH * 2 + laneB;
#pragma unroll
      for (int ks = 0; ks < 8; ks++) {
        uint32_t a[2][4];
        LDM4(a[0][0], a[0][1], a[0][2], a[0][3], abase + ks * 32);
        LDM4(a[1][0], a[1][1], a[1][2], a[1][3], abase + 16 * APITCH * 2 + ks * 32);
#pragma unroll
        for (int nt2 = 0; nt2 < 8; nt2++) {
          uint32_t b0, b1, b2, b3;
          LDM4(b0, b1, b2, b3, bbase + (uint32_t)(nt2 * 16) * BPITCH * 2 + ks * 32);
          MMA16816(acc[0][2 * nt2],     a[0], b0, b1);
          MMA16816(acc[0][2 * nt2 + 1], a[0], b2, b3);
          MMA16816(acc[1][2 * nt2],     a[1], b0, b1);
          MMA16816(acc[1][2 * nt2 + 1], a[1], b2, b3);
        }
      }
    }

    // direct epilogue: dense tile writes, L2 merges sectors (measured best)
#pragma unroll
    for (int mt = 0; mt < 2; mt++) {
#pragma unroll
      for (int nt = 0; nt < 16; nt++) {
        int row = m0 + warp_m * 32 + mt * 16 + er;
        int col = warp_n * 128 + nt * 8 + ec;
        *(float2*)(zx_buf + (size_t)row * 256 + col)       = make_float2(acc[mt][nt][0], acc[mt][nt][1]);
        *(float2*)(zx_buf + (size_t)(row + 8) * 256 + col) = make_float2(acc[mt][nt][2], acc[mt][nt][3]);
      }
    }
    __syncthreads();
  }
}

// ======== Kernel 2: recurrent LN-LSTM, 256 CTAs x 256 thr (8 rows), 2 CTAs/SM ========
// 4 warps/SMSP. GEMM: lane bits b0=qlow, b1b2=rp, b3b4=kt (K quartered, 16 k each).
// Wh pitch 264 + 8-float rotation per k-quarter => warp's 8 W granules hit all 32 banks.
#define NR2  8
#define HP   68
#define ZXP  264
#define WP   264
#define ZP   264

#define SM2_W     0                              // (64*264+32)*4 = 67712
#define SM2_ZX    67712                          // 2*8*264*4 = 16896
#define SM2_HBUF  (SM2_ZX + 2*NR2*ZXP*4)         // +2176
#define SM2_Z     (SM2_HBUF + NR2*HP*4)          // +8448
#define SM2_TOTAL (SM2_Z + NR2*ZP*4)             // 95,232 B per CTA (x2/SM = 190,464)

__device__ __forceinline__ void load_zx_async(float* dst, int n0, int t, int tid) {
#pragma unroll
  for (int it = 0; it < 2; it++) {
    int idx = tid + it * 256;
    int row = idx >> 6, cc = idx & 63;        // 8 rows x 64 chunks
    const float* src = zx_buf + ((size_t)(n0 + row) * 256 + t) * 256 + cc * 4;
    uint32_t da = smem_u32(dst + row * ZXP + cc * 4);
    asm volatile("cp.async.ca.shared.global [%0], [%1], 16;" :: "r"(da), "l"(src));
  }
}

__global__ void __launch_bounds__(256, 2)
critic_recur_kernel(const float* __restrict__ Wg,   const float* __restrict__ gamma,
                    const float* __restrict__ beta, const float* __restrict__ dW,
                    const float* __restrict__ db,   float* __restrict__ out) {
  extern __shared__ char smem[];
  float* Wsh  = (float*)(smem + SM2_W);
  float* zxs  = (float*)(smem + SM2_ZX);
  float* hbuf = (float*)(smem + SM2_HBUF);
  float* Z    = (float*)(smem + SM2_Z);

  const int tid  = threadIdx.x;
  const int lane = tid & 31, wrp = tid >> 5;      // 8 warps
  // GEMM mapping
  const int qlow = lane & 1;
  const int rp   = (lane >> 1) & 3;               // row pair: rows 2rp, 2rp+1
  const int kt   = (lane >> 3) & 3;               // K-quarter (16 k each)
  const int q    = 2 * wrp + qlow;                // colgroup 0..15
  const int n0   = blockIdx.x * NR2;

  // Stage Wh = Wg rows 128..191; pitch 264, +8-float rotation per k-quarter
  for (int i = tid; i < 64 * 256; i += 256) {
    int k = i >> 8, c = i & 255;
    Wsh[k * WP + 8 * (k >> 4) + c] = Wg[(size_t)(128 + k) * 256 + c];
  }
  for (int i = tid; i < NR2 * HP; i += 256) hbuf[i] = 0.f;

  load_zx_async(zxs, n0, 0, tid);
  asm volatile("cp.async.commit_group;");

  // LN-phase constants: warp wrp owns row wrp; lane covers cols 2*lane, 2*lane+1
  float2 gam[5], bet[5], dwr;
#pragma unroll
  for (int g = 0; g < 5; g++) {
    gam[g] = *(const float2*)(gamma + g * 64 + 2 * lane);
    bet[g] = *(const float2*)(beta  + g * 64 + 2 * lane);
  }
  dwr = *(const float2*)(dW + 2 * lane);
  const float dbr = db[0];

  const float* wB  = Wsh + kt * (16 * WP + 8) + 4 * q;
  const float* hB0 = hbuf + (2 * rp) * HP + kt * 16;
  const float* hB1 = hbuf + (2 * rp + 1) * HP + kt * 16;

  float2 cstate = make_float2(0.f, 0.f);   // post-LN c for (row=wrp, cols 2lane..2lane+1)
  asm volatile("cp.async.wait_group 0;");
  __syncthreads();

  for (int t = 0; t < TSTEPS; t++) {
    const int cur = t & 1;
    if (t + 1 < TSTEPS) load_zx_async(zxs + (cur ^ 1) * NR2 * ZXP, n0, t + 1, tid);
    asm volatile("cp.async.commit_group;");

    // ---- h @ Wh: 2 rows x 16 cols, 16 k per K-quarter ----
    unsigned long long acc0[8], acc1[8];
#pragma unroll
    for (int i = 0; i < 8; i++) { acc0[i] = 0ull; acc1[i] = 0ull; }
#pragma unroll
    for (int k = 0; k < 16; k += 4) {
      float4 a4 = *(const float4*)(hB0 + k);
      float4 b4 = *(const float4*)(hB1 + k);
      float xa[4] = {a4.x, a4.y, a4.z, a4.w};
      float xb[4] = {b4.x, b4.y, b4.z, b4.w};
#pragma unroll
      for (int kk = 0; kk < 4; kk++) {
        unsigned long long ua = pack2(xa[kk], xa[kk]);
        unsigned long long ub = pack2(xb[kk], xb[kk]);
        const float* wr = wB + (k + kk) * WP;
#pragma unroll
        for (int g = 0; g < 4; g++) {
          ulonglong2 wv = *(const ulonglong2*)(wr + g * 64);
          FMA2(acc0[2*g],   ua, wv.x);  FMA2(acc0[2*g+1], ua, wv.y);
          FMA2(acc1[2*g],   ub, wv.x);  FMA2(acc1[2*g+1], ub, wv.y);
        }
      }
    }
    // split-K combine over lane bits 3,4 (kt)
#pragma unroll
    for (int i = 0; i < 8; i++) {
      unsigned long long o;
      o = __shfl_xor_sync(0xffffffffu, acc0[i], 8);  ADD2(acc0[i], o);
      o = __shfl_xor_sync(0xffffffffu, acc0[i], 16); ADD2(acc0[i], o);
      o = __shfl_xor_sync(0xffffffffu, acc1[i], 8);  ADD2(acc1[i], o);
      o = __shfl_xor_sync(0xffffffffu, acc1[i], 16); ADD2(acc1[i], o);
    }

    // writers (kt == rp) store both rows to Z transpose buffer
    if (kt == rp) {
#pragma unroll
      for (int g = 0; g < 4; g++) {
        float2 a0 = unpack2(acc0[2*g]), b0 = unpack2(acc0[2*g+1]);
        float2 a1 = unpack2(acc1[2*g]), b1 = unpack2(acc1[2*g+1]);
        *(float4*)(Z + (2*rp)     * ZP + g * 64 + 4 * q) = make_float4(a0.x, a0.y, b0.x, b0.y);
        *(float4*)(Z + (2*rp + 1) * ZP + g * 64 + 4 * q) = make_float4(a1.x, a1.y, b1.x, b1.y);
      }
    }
    __syncthreads();

    // ---- LN phase: warp wrp owns row wrp; 2 cols per lane; full-warp shfl reductions ----
    const float* zr  = Z + wrp * ZP;
    const float* zxr = zxs + cur * NR2 * ZXP + wrp * ZXP;
    float2 z[4], st[4];
#pragma unroll
    for (int g = 0; g < 4; g++) {
      float2 a = *(const float2*)(zr  + g * 64 + 2 * lane);
      float2 b = *(const float2*)(zxr + g * 64 + 2 * lane);
      z[g].x = a.x + b.x; z[g].y = a.y + b.y;
      float s  = z[g].x + z[g].y;
      float ss = z[g].x * z[g].x + z[g].y * z[g].y;
      unsigned long long p = pack2(s, ss);
#pragma unroll
      for (int m = 16; m >= 1; m >>= 1) {
        unsigned long long o = __shfl_xor_sync(0xffffffffu, p, m); ADD2(p, o);
      }
      float2 sv = unpack2(p);
      float mu = sv.x * 0.015625f;
      float var = fmaxf(sv.y * 0.015625f - mu * mu, 0.f);
      st[g] = make_float2(mu, rsqrtf(var + 1e-12f));
    }

    float2 nc, on;
    {
      float zi0 = (z[0].x - st[0].x) * st[0].y * gam[0].x + bet[0].x;
      float zi1 = (z[0].y - st[0].x) * st[0].y * gam[0].y + bet[0].y;
      float zj0 = (z[1].x - st[1].x) * st[1].y * gam[1].x + bet[1].x;
      float zj1 = (z[1].y - st[1].x) * st[1].y * gam[1].y + bet[1].y;
      float zf0 = (z[2].x - st[2].x) * st[2].y * gam[2].x + bet[2].x;
      float zf1 = (z[2].y - st[2].x) * st[2].y * gam[2].y + bet[2].y;
      on.x      = (z[3].x - st[3].x) * st[3].y * gam[3].x + bet[3].x;
      on.y      = (z[3].y - st[3].x) * st[3].y * gam[3].y + bet[3].y;
      nc.x = cstate.x * sigm(zf0 + 1.f) + sigm(zi0) * tanhx(zj0);   // forget_bias = 1
      nc.y = cstate.y * sigm(zf1 + 1.f) + sigm(zi1) * tanhx(zj1);
    }
    {
      float cs = nc.x + nc.y, css = nc.x * nc.x + nc.y * nc.y;
      unsigned long long p = pack2(cs, css);
#pragma unroll
      for (int m = 16; m >= 1; m >>= 1) {
        unsigned long long o = __shfl_xor_sync(0xffffffffu, p, m); ADD2(p, o);
      }
      float2 sv = unpack2(p);
      float mu = sv.x * 0.015625f;
      float var = fmaxf(sv.y * 0.015625f - mu * mu, 0.f);
      float rstd = rsqrtf(var + 1e-12f);
      float cn0 = (nc.x - mu) * rstd * gam[4].x + bet[4].x;
      float cn1 = (nc.y - mu) * rstd * gam[4].y + bet[4].y;
      cstate.x = cn0; cstate.y = cn1;
      float h0 = tanhx(cn0) * sigm(on.x);
      float h1 = tanhx(cn1) * sigm(on.y);
      *(float2*)(hbuf + wrp * HP + 2 * lane) = make_float2(h0, h1);
      float qp = h0 * dwr.x + h1 * dwr.y;
#pragma unroll
      for (int m = 16; m >= 1; m >>= 1) qp += __shfl_xor_sync(0xffffffffu, qp, m);
      if (lane == 0) out[(size_t)(n0 + wrp) * TSTEPS + t] = dbr + qp;
    }

    asm volatile("cp.async.wait_group 0;");   // next zx staged
    __syncthreads();                          // h + zx visible for next step
  }
}

extern "C" void kernel_launch(void* const* d_in, const int* in_sizes, int n_in,
                              void* d_out, int out_size) {
  const float* obss  = (const float*)d_in[0];
  const float* acts  = (const float*)d_in[1];
  const float* W     = (const float*)d_in[2];
  const float* gamma = (const float*)d_in[3];
  const float* beta  = (const float*)d_in[4];
  const float* dW    = (const float*)d_in[5];
  const float* db    = (const float*)d_in[6];
  float* out = (float*)d_out;

  cudaFuncSetAttribute(zx_gemm_kernel, cudaFuncAttributeMaxDynamicSharedMemorySize, K1_TOTAL);
  cudaFuncSetAttribute(critic_recur_kernel, cudaFuncAttributeMaxDynamicSharedMemorySize, SM2_TOTAL);
  zx_gemm_kernel<<<148, 256, K1_TOTAL>>>(obss, acts, W);
  critic_recur_kernel<<<256, 256, SM2_TOTAL>>>(W, gamma, beta, dW, db, out);
}